// round 13
// baseline (speedup 1.0000x reference)
#include <cuda_runtime.h>
#include <cuda_fp16.h>
#include <math.h>
#include <stdint.h>

#define HDIM 72
#define NSEQ 256
#define BATCH 16
#define ROWS 4096          // BATCH*NSEQ
#define SDIM 13
#define HP 88              // half pitch: row-start bank (44r)%32 distinct -> ldmatrix conflict-free

// ---------------- device scratch (static, no runtime alloc) ----------------
__device__ float  d_A [ROWS*HDIM];
__device__ float  d_Bm[ROWS*HDIM];      // UNSCALED (scale folded into k_main build)
__device__ float  d_Rn[ROWS];
__device__ float  d_Rd[ROWS];
__device__ float  d_S5[5];              // Sn, Sd, Snn, Sdd, Snd
__device__ float  d_SA[BATCH*HDIM];     // atomic accum (zeroed in k_zero)
__device__ float  d_SB[BATCH*HDIM];
__device__ float  d_T6[6*HDIM];
__device__ float  d_bn1[2*HDIM];        // scale, shift
__device__ float  d_r1s[HDIM];          // sc*r1
__device__ float  d_r2s[HDIM];          // sc*r2
__device__ float  d_magg[ROWS*HDIM];
__device__ float  d_y0 [ROWS*HDIM];
__device__ float  d_bn2[2*HDIM];
__device__ float  d_bn2acc[2*HDIM];     // sum, sumsq of y0 per channel
__device__ __align__(16) __half d_W2h[HDIM*HP];   // We2^T fp16 [n][k], k padded
__device__ __align__(16) __half d_W1h[HDIM*HP];   // Wx1^T fp16 [n][k]

__device__ __forceinline__ float psif(float x){
    return copysignf(log1pf(fabsf(x)), x);
}
__device__ __forceinline__ float wsum(float v){
    v += __shfl_xor_sync(0xffffffffu, v, 16);
    v += __shfl_xor_sync(0xffffffffu, v, 8);
    v += __shfl_xor_sync(0xffffffffu, v, 4);
    v += __shfl_xor_sync(0xffffffffu, v, 2);
    v += __shfl_xor_sync(0xffffffffu, v, 1);
    return v;
}
__device__ __forceinline__ uint32_t smem_u32(const void* p){
    uint32_t a;
    asm("{ .reg .u64 t; cvta.to.shared.u64 t, %1; cvt.u32.u64 %0, t; }" : "=r"(a) : "l"(p));
    return a;
}
__device__ __forceinline__ void mma16(float* c, uint32_t a0, uint32_t a1, uint32_t a2,
                                      uint32_t a3, uint32_t b0, uint32_t b1){
    asm volatile("mma.sync.aligned.m16n8k16.row.col.f32.f16.f16.f32 "
        "{%0,%1,%2,%3}, {%4,%5,%6,%7}, {%8,%9}, {%0,%1,%2,%3};"
        : "+f"(c[0]), "+f"(c[1]), "+f"(c[2]), "+f"(c[3])
        : "r"(a0), "r"(a1), "r"(a2), "r"(a3), "r"(b0), "r"(b1));
}
__device__ __forceinline__ void ldsm_x4(uint32_t& r0, uint32_t& r1, uint32_t& r2,
                                        uint32_t& r3, uint32_t addr){
    asm volatile("ldmatrix.sync.aligned.m8n8.x4.shared.b16 {%0,%1,%2,%3}, [%4];"
        : "=r"(r0), "=r"(r1), "=r"(r2), "=r"(r3) : "r"(addr));
}
__device__ __forceinline__ void ldsm_x2(uint32_t& r0, uint32_t& r1, uint32_t addr){
    asm volatile("ldmatrix.sync.aligned.m8n8.x2.shared.b16 {%0,%1}, [%2];"
        : "=r"(r0), "=r"(r1) : "r"(addr));
}

// ---------------- zero accumulators + fp16 weight transpose ----------------
__global__ void k_zero(const float* __restrict__ We2, const float* __restrict__ Wx1){
    int t = blockIdx.x*256 + threadIdx.x;    // grid 8 x 256 = 2048
    if (t < 5) d_S5[t] = 0.f;
    for (int i = t; i < 6*HDIM; i += 2048) d_T6[i] = 0.f;
    for (int i = t; i < 2*HDIM; i += 2048) d_bn2acc[i] = 0.f;
    for (int i = t; i < BATCH*HDIM; i += 2048){ d_SA[i] = 0.f; d_SB[i] = 0.f; }
    for (int i = t; i < HDIM*80; i += 2048){
        int k = i / HDIM, n = i - (i/HDIM)*HDIM;
        __half w2 = (k < HDIM) ? __float2half_rn(We2[k*HDIM + n]) : __half(0.f);
        __half w1 = (k < HDIM) ? __float2half_rn(Wx1[k*HDIM + n]) : __half(0.f);
        d_W2h[n*HP + k] = w2;
        d_W1h[n*HP + k] = w1;
    }
}

// ---------------- geometry moments ----------------
__global__ void k_geom(const float* __restrict__ p){
    int i = blockIdx.x, b = blockIdx.y;
    int row = b*NSEQ + i;
    int j = threadIdx.x;
    __shared__ float4 pi4s;
    __shared__ float red[8][5];
    if (j == 0) pi4s = reinterpret_cast<const float4*>(p)[row];
    __syncthreads();
    float4 pi = pi4s;
    float4 pj = reinterpret_cast<const float4*>(p)[b*NSEQ + j];
    float d0=pi.x-pj.x, d1=pi.y-pj.y, d2=pi.z-pj.z, d3=pi.w-pj.w;
    float n  = psif(d1*d1 + d2*d2 + d3*d3 - d0*d0);
    float dt = psif(pi.x*pj.x - pi.y*pj.y - pi.z*pj.z - pi.w*pj.w);
    float v0=wsum(n), v1=wsum(dt), v2=wsum(n*n), v3=wsum(dt*dt), v4=wsum(n*dt);
    int lane = j & 31, w = j >> 5;
    if (lane==0){ red[w][0]=v0; red[w][1]=v1; red[w][2]=v2; red[w][3]=v3; red[w][4]=v4; }
    __syncthreads();
    if (j == 0){
        float s0=0,s1=0,s2=0,s3=0,s4=0;
        for (int q=0;q<8;q++){ s0+=red[q][0]; s1+=red[q][1]; s2+=red[q][2]; s3+=red[q][3]; s4+=red[q][4]; }
        d_Rn[row]=s0; d_Rd[row]=s1;
        atomicAdd(&d_S5[0], s0); atomicAdd(&d_S5[1], s1);
        atomicAdd(&d_S5[2], s2); atomicAdd(&d_S5[3], s3); atomicAdd(&d_S5[4], s4);
    }
}

// ---------------- A/B (8 rows/block) + fused per-channel moments ----------------
__global__ void k_AB(const float* __restrict__ h, const float* __restrict__ We1){
    __shared__ float Ws[144*HDIM];
    __shared__ float hs[8*HDIM];
    __shared__ float rnS[8], rdS[8];
    int t = threadIdx.x;   // 256
    int row0 = blockIdx.x*8;
    int b = blockIdx.x >> 5;            // 32 blocks per batch
    for (int idx=t; idx<144*HDIM; idx+=256) Ws[idx] = We1[idx];
    for (int idx=t; idx<8*HDIM; idx+=256)   hs[idx] = h[row0*HDIM + idx];
    if (t < 8){ rnS[t] = d_Rn[row0 + t]; rdS[t] = d_Rd[row0 + t]; }
    __syncthreads();
    if (t < 144){
        bool isA = t < HDIM;
        int c = isA ? t : t - HDIM;
        const float* Wcol = Ws + (isA ? 0 : HDIM*HDIM) + c;
        float sum=0.f, sq=0.f, srn=0.f, srd=0.f;
        #pragma unroll 2
        for (int r=0;r<8;r++){
            const float* hr = hs + r*HDIM;
            float acc = 0.f;
            #pragma unroll 8
            for (int k=0;k<HDIM;k++) acc = fmaf(hr[k], Wcol[k*HDIM], acc);
            if (isA) d_A [(row0+r)*HDIM + c] = acc;
            else     d_Bm[(row0+r)*HDIM + c] = acc;
            sum += acc;
            sq  = fmaf(acc, acc, sq);
            srn = fmaf(acc, rnS[r], srn);
            srd = fmaf(acc, rdS[r], srd);
        }
        if (isA){
            atomicAdd(&d_SA[b*HDIM + c], sum);
            atomicAdd(&d_T6[0*HDIM + c], sq);
            atomicAdd(&d_T6[2*HDIM + c], srn);
            atomicAdd(&d_T6[3*HDIM + c], srd);
        } else {
            atomicAdd(&d_SB[b*HDIM + c], sum);
            atomicAdd(&d_T6[1*HDIM + c], sq);
            atomicAdd(&d_T6[4*HDIM + c], srn);
            atomicAdd(&d_T6[5*HDIM + c], srd);
        }
    }
}

// ---------------- BN1 finalize (exact algebra) + fold sc into r1,r2 ----------------
__global__ void k_bn1(const float* __restrict__ We1, const float* __restrict__ g1,
                      const float* __restrict__ b1){
    int c = threadIdx.x;
    if (c >= HDIM) return;
    float r1 = We1[144*HDIM + c], r2 = We1[145*HDIM + c];
    float SAt=0.f, SBt=0.f, cross=0.f;
    for (int b=0;b<BATCH;b++){
        float sa = d_SA[b*HDIM+c], sb = d_SB[b*HDIM+c];
        SAt += sa; SBt += sb; cross += sa*sb;
    }
    float Sn=d_S5[0], Sd=d_S5[1], Snn=d_S5[2], Sdd=d_S5[3], Snd=d_S5[4];
    float sumx  = 256.f*(SAt + SBt) + r1*Sn + r2*Sd;
    float sumx2 = 256.f*(d_T6[c] + d_T6[HDIM+c])
                + r1*r1*Snn + r2*r2*Sdd
                + 2.f*cross
                + 2.f*r1*(d_T6[2*HDIM+c] + d_T6[4*HDIM+c])
                + 2.f*r2*(d_T6[3*HDIM+c] + d_T6[5*HDIM+c])
                + 2.f*r1*r2*Snd;
    const float P = 1048576.f;
    float mu  = sumx / P;
    float var = sumx2 / P - mu*mu;
    float sc  = g1[c] * rsqrtf(var + 1e-5f);
    d_bn1[c]        = sc;
    d_bn1[HDIM + c] = b1[c] - mu*sc;
    d_r1s[c] = r1*sc;
    d_r2s[c] = r2*sc;
}

// ---------------- main pairwise kernel ----------------
// SMEM: Ts[256][HP] half | W2c[72][HP] half | W1c[72][HP] half | vectors
#define TS_OFF  0
#define TS_BYTES (256*HP*2)
#define W2_OFF  (TS_OFF + TS_BYTES)
#define W1_OFF  (W2_OFF + HDIM*HP*2)
#define VEC_OFF (W1_OFF + HDIM*HP*2)

struct KVecs {
    float Ash[HDIM], Scv[HDIM], r1s[HDIM], r2s[HDIM];
    float be2v[HDIM], bx1v[HDIM], Wmv[HDIM], Wx2v[HDIM];
    float mg[HDIM];
    float aggred[8][4];
    float pis[4];
    float bmv;
};
#define KSMEM_TOTAL (VEC_OFF + (int)sizeof(KVecs))

__global__ __launch_bounds__(256, 3) void k_main(
    const float* __restrict__ p,
    const float* __restrict__ be2, const float* __restrict__ Wm,
    const float* __restrict__ bm,  const float* __restrict__ bx1,
    const float* __restrict__ Wx2, float* __restrict__ out_p)
{
    extern __shared__ unsigned char sm[];
    __half* Ts  = reinterpret_cast<__half*>(sm + TS_OFF);
    __half* W2c = reinterpret_cast<__half*>(sm + W2_OFF);
    __half* W1c = reinterpret_cast<__half*>(sm + W1_OFF);
    KVecs*  V   = reinterpret_cast<KVecs*>(sm + VEC_OFF);
    const int i = blockIdx.x, b = blockIdx.y;
    const int row = b*NSEQ + i;
    const int tid  = threadIdx.x;
    const int wid  = tid >> 5;       // 0..7
    const int lane = tid & 31;
    const int g    = lane >> 2;
    const int tig  = lane & 3;
    const int r0   = wid*32;         // warp's 32 rows

    // ---- init: copy pre-transposed fp16 weights, vectors, pad ----
    {
        uint4* dst2 = reinterpret_cast<uint4*>(W2c);
        uint4* dst1 = reinterpret_cast<uint4*>(W1c);
        const uint4* s2 = reinterpret_cast<const uint4*>(d_W2h);
        const uint4* s1 = reinterpret_cast<const uint4*>(d_W1h);
        for (int t = tid; t < HDIM*HP/8; t += 256){ dst2[t] = s2[t]; dst1[t] = s1[t]; }
    }
    *reinterpret_cast<uint4*>(Ts + tid*HP + 72) = make_uint4(0u,0u,0u,0u);  // K pad
    if (tid < HDIM){
        float sc = d_bn1[tid];
        V->Ash[tid]  = fmaf(d_A[row*HDIM + tid], sc, d_bn1[HDIM + tid]);
        V->Scv[tid]  = sc;
        V->r1s[tid]  = d_r1s[tid];
        V->r2s[tid]  = d_r2s[tid];
        V->be2v[tid] = be2[tid];
        V->bx1v[tid] = bx1[tid];
        V->Wmv[tid]  = Wm[tid];
        V->Wx2v[tid] = Wx2[tid];
        V->mg[tid]   = 0.f;
    }
    if (tid < 4)  V->pis[tid] = p[row*4 + tid];
    if (tid == 0) V->bmv = bm[0];
    __syncthreads();

    const float bmv = V->bmv;
    const float4 pis4 = *reinterpret_cast<const float4*>(V->pis);

    // ---- build all 256 rows: thread t builds row t (scale of Bm folded in) ----
    {
        float4 pj = reinterpret_cast<const float4*>(p)[b*NSEQ + tid];
        float e0=pis4.x-pj.x, e1=pis4.y-pj.y, e2=pis4.z-pj.z, e3=pis4.w-pj.w;
        float nn = psif(e1*e1 + e2*e2 + e3*e3 - e0*e0);
        float dd = psif(pis4.x*pj.x - pis4.y*pj.y - pis4.z*pj.z - pis4.w*pj.w);
        const float4* B4 = reinterpret_cast<const float4*>(d_Bm + (b*NSEQ + tid)*HDIM);
        const float4* A4 = reinterpret_cast<const float4*>(V->Ash);
        const float4* S4 = reinterpret_cast<const float4*>(V->Scv);
        const float4* U4 = reinterpret_cast<const float4*>(V->r1s);
        const float4* W4 = reinterpret_cast<const float4*>(V->r2s);
        #pragma unroll
        for (int q = 0; q < 18; ++q){
            float4 bv = B4[q];
            float4 av = A4[q], sv = S4[q], uv = U4[q], wv = W4[q];
            float v0 = fmaxf(fmaf(sv.x, bv.x, av.x) + nn*uv.x + dd*wv.x, 0.f);
            float v1 = fmaxf(fmaf(sv.y, bv.y, av.y) + nn*uv.y + dd*wv.y, 0.f);
            float v2 = fmaxf(fmaf(sv.z, bv.z, av.z) + nn*uv.z + dd*wv.z, 0.f);
            float v3 = fmaxf(fmaf(sv.w, bv.w, av.w) + nn*uv.w + dd*wv.w, 0.f);
            __half2 hlo = __floats2half2_rn(v0, v1);
            __half2 hhi = __floats2half2_rn(v2, v3);
            uint2 u; u.x = *reinterpret_cast<uint32_t*>(&hlo); u.y = *reinterpret_cast<uint32_t*>(&hhi);
            *reinterpret_cast<uint2*>(Ts + tid*HP + q*4) = u;
        }
    }
    __syncwarp();

    // ldmatrix addresses
    const int lr  = lane & 15;
    const int kh  = (lane & 16) ? 8 : 0;
    uint32_t aAddr[2];
    aAddr[0] = smem_u32(Ts) + (uint32_t)(((r0 + lr)*HP + kh)*2);
    aAddr[1] = aAddr[0] + 16*HP*2;
    const int bl  = lane & 7;
    const int bko = (lane & 8) ? 8 : 0;
    const uint32_t b2Addr = smem_u32(W2c) + (uint32_t)((bl*HP + bko)*2);
    const uint32_t b1Addr = smem_u32(W1c) + (uint32_t)((bl*HP + bko)*2);

    float colsum[9][2];
    #pragma unroll
    for (int nt=0;nt<9;nt++){ colsum[nt][0]=0.f; colsum[nt][1]=0.f; }
    float agg0=0.f, agg1=0.f, agg2=0.f, agg3=0.f;

    // ======== GEMM1 + epi1, chunk-sequential (16 rows at a time) ========
    #pragma unroll
    for (int ch=0;ch<2;ch++){
        float acc[9][4];
        #pragma unroll
        for (int nt=0;nt<9;nt++){ acc[nt][0]=0.f; acc[nt][1]=0.f; acc[nt][2]=0.f; acc[nt][3]=0.f; }
        #pragma unroll
        for (int kk=0;kk<5;kk++){
            uint32_t a0,a1,a2,a3;
            ldsm_x4(a0,a1,a2,a3, aAddr[ch] + kk*32);
            #pragma unroll
            for (int nt=0;nt<9;nt++){
                uint32_t b0,b1;
                ldsm_x2(b0,b1, b2Addr + nt*(8*HP*2) + kk*32);
                mma16(acc[nt], a0,a1,a2,a3, b0,b1);
            }
        }
        // epi1: m = relu(acc+be2); w = sigmoid(m.Wm+bm); wm = m*w -> Ts
        float dot0 = 0.f, dot1 = 0.f;
        #pragma unroll
        for (int nt=0;nt<9;nt++){
            int cb = nt*8 + 2*tig;
            float2 bb = *reinterpret_cast<const float2*>(V->be2v + cb);
            float2 wm2 = *reinterpret_cast<const float2*>(V->Wmv + cb);
            float m0 = fmaxf(acc[nt][0] + bb.x, 0.f);
            float m1 = fmaxf(acc[nt][1] + bb.y, 0.f);
            float m2 = fmaxf(acc[nt][2] + bb.x, 0.f);
            float m3 = fmaxf(acc[nt][3] + bb.y, 0.f);
            acc[nt][0]=m0; acc[nt][1]=m1; acc[nt][2]=m2; acc[nt][3]=m3;
            dot0 = fmaf(m0, wm2.x, fmaf(m1, wm2.y, dot0));
            dot1 = fmaf(m2, wm2.x, fmaf(m3, wm2.y, dot1));
        }
        dot0 += __shfl_xor_sync(0xffffffffu, dot0, 1);
        dot0 += __shfl_xor_sync(0xffffffffu, dot0, 2);
        dot1 += __shfl_xor_sync(0xffffffffu, dot1, 1);
        dot1 += __shfl_xor_sync(0xffffffffu, dot1, 2);
        float w0 = 1.f / (1.f + expf(-(dot0 + bmv)));
        float w1 = 1.f / (1.f + expf(-(dot1 + bmv)));
        const int rl = r0 + ch*16 + g;
        #pragma unroll
        for (int nt=0;nt<9;nt++){
            float l0 = acc[nt][0]*w0;
            float l1 = acc[nt][1]*w0;
            float h0 = acc[nt][2]*w1;
            float h1 = acc[nt][3]*w1;
            colsum[nt][0] += l0 + h0;
            colsum[nt][1] += l1 + h1;
            int cb = nt*8 + 2*tig;
            __half2 lo = __floats2half2_rn(l0, l1);
            __half2 hi = __floats2half2_rn(h0, h1);
            *reinterpret_cast<uint32_t*>(Ts + rl*HP + cb)     = *reinterpret_cast<uint32_t*>(&lo);
            *reinterpret_cast<uint32_t*>(Ts + (rl+8)*HP + cb) = *reinterpret_cast<uint32_t*>(&hi);
        }
    }
    __syncwarp();

    // ======== GEMM2 + epi2, chunk-sequential ========
    #pragma unroll
    for (int ch=0;ch<2;ch++){
        float acc[9][4];
        #pragma unroll
        for (int nt=0;nt<9;nt++){ acc[nt][0]=0.f; acc[nt][1]=0.f; acc[nt][2]=0.f; acc[nt][3]=0.f; }
        #pragma unroll
        for (int kk=0;kk<5;kk++){
            uint32_t a0,a1,a2,a3;
            ldsm_x4(a0,a1,a2,a3, aAddr[ch] + kk*32);
            #pragma unroll
            for (int nt=0;nt<9;nt++){
                uint32_t b0,b1;
                ldsm_x2(b0,b1, b1Addr + nt*(8*HP*2) + kk*32);
                mma16(acc[nt], a0,a1,a2,a3, b0,b1);
            }
        }
        // epi2: u = relu(acc+bx1); xw = u.Wx2; tig0 lanes do their rows' aggs
        float px0 = 0.f, px1 = 0.f;
        #pragma unroll
        for (int nt=0;nt<9;nt++){
            int cb = nt*8 + 2*tig;
            float2 bb = *reinterpret_cast<const float2*>(V->bx1v + cb);
            float2 wx = *reinterpret_cast<const float2*>(V->Wx2v + cb);
            float u0 = fmaxf(acc[nt][0] + bb.x, 0.f);
            float u1 = fmaxf(acc[nt][1] + bb.y, 0.f);
            float u2 = fmaxf(acc[nt][2] + bb.x, 0.f);
            float u3 = fmaxf(acc[nt][3] + bb.y, 0.f);
            px0 = fmaf(u0, wx.x, fmaf(u1, wx.y, px0));
            px1 = fmaf(u2, wx.x, fmaf(u3, wx.y, px1));
        }
        px0 += __shfl_xor_sync(0xffffffffu, px0, 1);
        px0 += __shfl_xor_sync(0xffffffffu, px0, 2);
        px1 += __shfl_xor_sync(0xffffffffu, px1, 1);
        px1 += __shfl_xor_sync(0xffffffffu, px1, 2);
        if (tig == 0){
            int jl = r0 + ch*16 + g;
            float4 pj = reinterpret_cast<const float4*>(p)[b*NSEQ + jl];
            agg0 += fminf(fmaxf((pis4.x - pj.x)*px0, -100.f), 100.f);
            agg1 += fminf(fmaxf((pis4.y - pj.y)*px0, -100.f), 100.f);
            agg2 += fminf(fmaxf((pis4.z - pj.z)*px0, -100.f), 100.f);
            agg3 += fminf(fmaxf((pis4.w - pj.w)*px0, -100.f), 100.f);
            float4 ph = reinterpret_cast<const float4*>(p)[b*NSEQ + jl + 8];
            agg0 += fminf(fmaxf((pis4.x - ph.x)*px1, -100.f), 100.f);
            agg1 += fminf(fmaxf((pis4.y - ph.y)*px1, -100.f), 100.f);
            agg2 += fminf(fmaxf((pis4.z - ph.z)*px1, -100.f), 100.f);
            agg3 += fminf(fmaxf((pis4.w - ph.w)*px1, -100.f), 100.f);
        }
    }

    // ---- magg: reduce colsum over g-lanes, atomic into V->mg ----
    #pragma unroll
    for (int nt=0;nt<9;nt++)
        #pragma unroll
        for (int d=0;d<2;d++){
            float v = colsum[nt][d];
            v += __shfl_xor_sync(0xffffffffu, v, 4);
            v += __shfl_xor_sync(0xffffffffu, v, 8);
            v += __shfl_xor_sync(0xffffffffu, v, 16);
            if (g == 0) atomicAdd(&V->mg[nt*8 + 2*tig + d], v);
        }
    // ---- agg reduce across warps ----
    {
        float s0=wsum(agg0), s1=wsum(agg1), s2=wsum(agg2), s3=wsum(agg3);
        if (lane==0){ V->aggred[wid][0]=s0; V->aggred[wid][1]=s1; V->aggred[wid][2]=s2; V->aggred[wid][3]=s3; }
    }
    __syncthreads();
    if (tid < HDIM) d_magg[row*HDIM + tid] = V->mg[tid];
    if (tid < 4){
        float s = 0.f;
        #pragma unroll
        for (int w=0;w<8;w++) s += V->aggred[w][tid];
        out_p[row*4 + tid] = V->pis[tid] + (s * (1.f/256.f)) * 0.001f;
    }
}

// ---------------- h-path: y0 = [h,magg,s] @ Wh1 + bh1 (64 rows/block, tiled) ----
__global__ __launch_bounds__(256) void k_y0(
    const float* __restrict__ h, const float* __restrict__ s,
    const float* __restrict__ Wh1, const float* __restrict__ bh1)
{
    extern __shared__ float ysm[];
    float* Ws   = ysm;                 // 157*72
    float* hinS = ysm + 157*HDIM;      // 64 rows, pitch 161
    int t = threadIdx.x;
    int row0 = blockIdx.x * 64;
    for (int idx = t; idx < 157*HDIM; idx += 256) Ws[idx] = Wh1[idx];
    for (int idx = t; idx < 64*HDIM; idx += 256){
        int r = idx / HDIM, c = idx - r*HDIM;
        hinS[r*161 + c]        = h[(row0+r)*HDIM + c];
        hinS[r*161 + HDIM + c] = d_magg[(row0+r)*HDIM + c];
    }
    for (int idx = t; idx < 64*SDIM; idx += 256){
        int r = idx / SDIM, c = idx - r*SDIM;
        hinS[r*161 + 2*HDIM + c] = s[(row0+r)*SDIM + c];
    }
    __syncthreads();
    int tr = t & 31, cg = t >> 5;
    int c0 = cg*9;
    float acc0[9], acc1[9];
    #pragma unroll
    for (int m=0;m<9;m++){ float bv = bh1[c0+m]; acc0[m] = bv; acc1[m] = bv; }
    const float* h0p = hinS + tr*161;
    const float* h1p = hinS + (tr+32)*161;
    #pragma unroll 4
    for (int k=0;k<157;k++){
        float x0 = h0p[k], x1 = h1p[k];
        const float* wr = Ws + k*HDIM + c0;
        #pragma unroll
        for (int m=0;m<9;m++){ float w = wr[m]; acc0[m] = fmaf(x0,w,acc0[m]); acc1[m] = fmaf(x1,w,acc1[m]); }
    }
    #pragma unroll
    for (int m=0;m<9;m++){
        d_y0[(row0+tr)*HDIM + c0+m]    = acc0[m];
        d_y0[(row0+tr+32)*HDIM + c0+m] = acc1[m];
        float sv = acc0[m] + acc1[m];
        float qv = acc0[m]*acc0[m] + acc1[m]*acc1[m];
        sv = wsum(sv);
        qv = wsum(qv);
        if (tr == 0){
            atomicAdd(&d_bn2acc[c0+m], sv);
            atomicAdd(&d_bn2acc[HDIM + c0+m], qv);
        }
    }
}

// ---------------- BN2 finalize ----------------
__global__ void k_bn2f(const float* __restrict__ gh, const float* __restrict__ bh){
    int c = threadIdx.x;
    if (c >= HDIM) return;
    float mu  = d_bn2acc[c] / 4096.f;
    float var = d_bn2acc[HDIM + c] / 4096.f - mu*mu;
    float sc  = gh[c] * rsqrtf(var + 1e-5f);
    d_bn2[c]        = sc;
    d_bn2[HDIM + c] = bh[c] - mu*sc;
}

// ---------------- h_out = h + relu(bn2(y0)) @ Wh2 + bh2 (64 rows/block) ----------
__global__ __launch_bounds__(256) void k_hout(
    const float* __restrict__ h, const float* __restrict__ Wh2,
    const float* __restrict__ bh2, float* __restrict__ out_h)
{
    __shared__ float Ws[HDIM*HDIM];
    __shared__ float yrS[64*73];
    int t = threadIdx.x;
    int row0 = blockIdx.x * 64;
    for (int idx=t; idx<HDIM*HDIM; idx+=256) Ws[idx] = Wh2[idx];
    for (int idx=t; idx<64*HDIM; idx+=256){
        int r = idx / HDIM, c = idx - r*HDIM;
        yrS[r*73 + c] = fmaxf(fmaf(d_y0[(row0+r)*HDIM + c], d_bn2[c], d_bn2[HDIM + c]), 0.f);
    }
    __syncthreads();
    int tr = t & 31, cg = t >> 5;
    int c0 = cg*9;
    float acc0[9], acc1[9];
    #pragma unroll
    for (int m=0;m<9;m++){ float bv = bh2[c0+m]; acc0[m] = bv; acc1[m] = bv; }
    const float* y0p = yrS + tr*73;
    const float* y1p = yrS + (tr+32)*73;
    #pragma unroll 4
    for (int k=0;k<HDIM;k++){
        float x0 = y0p[k], x1 = y1p[k];
        const float* wr = Ws + k*HDIM + c0;
        #pragma unroll
        for (int m=0;m<9;m++){ float w = wr[m]; acc0[m] = fmaf(x0,w,acc0[m]); acc1[m] = fmaf(x1,w,acc1[m]); }
    }
    #pragma unroll
    for (int m=0;m<9;m++){
        out_h[(row0+tr)*HDIM + c0+m]    = h[(row0+tr)*HDIM + c0+m]    + acc0[m];
        out_h[(row0+tr+32)*HDIM + c0+m] = h[(row0+tr+32)*HDIM + c0+m] + acc1[m];
    }
}

// ---------------- launch ----------------
extern "C" void kernel_launch(void* const* d_in, const int* in_sizes, int n_in,
                              void* d_out, int out_size){
    const float* h   = (const float*)d_in[0];
    const float* p   = (const float*)d_in[1];
    const float* s   = (const float*)d_in[2];
    const float* We1 = (const float*)d_in[3];
    const float* g1  = (const float*)d_in[4];
    const float* b1  = (const float*)d_in[5];
    const float* We2 = (const float*)d_in[6];
    const float* be2 = (const float*)d_in[7];
    const float* Wm  = (const float*)d_in[8];
    const float* bm  = (const float*)d_in[9];
    const float* Wx1 = (const float*)d_in[10];
    const float* bx1 = (const float*)d_in[11];
    const float* Wx2 = (const float*)d_in[12];
    const float* Wh1 = (const float*)d_in[13];
    const float* bh1 = (const float*)d_in[14];
    const float* gh  = (const float*)d_in[15];
    const float* bh  = (const float*)d_in[16];
    const float* Wh2 = (const float*)d_in[17];
    const float* bh2 = (const float*)d_in[18];
    float* out   = (float*)d_out;
    float* out_h = out;                 // (B,N,H) first
    float* out_p = out + ROWS*HDIM;     // then (B,N,4)

    const int y0smem = (157*HDIM + 64*161) * 4;
    cudaFuncSetAttribute(k_main, cudaFuncAttributeMaxDynamicSharedMemorySize, KSMEM_TOTAL);
    cudaFuncSetAttribute(k_y0,   cudaFuncAttributeMaxDynamicSharedMemorySize, y0smem);

    k_zero <<<8, 256>>>(We2, Wx1);
    k_geom <<<dim3(NSEQ, BATCH), NSEQ>>>(p);
    k_AB   <<<ROWS/8, 256>>>(h, We1);
    k_bn1  <<<1, 128>>>(We1, g1, b1);
    k_main <<<dim3(NSEQ, BATCH), 256, KSMEM_TOTAL>>>(p, be2, Wm, bm, bx1, Wx2, out_p);
    k_y0   <<<ROWS/64, 256, y0smem>>>(h, s, Wh1, bh1);
    k_bn2f <<<1, 128>>>(gh, bh);
    k_hout <<<ROWS/64, 256>>>(h, Wh2, bh2, out_h);
}

// round 14
// speedup vs baseline: 1.1755x; 1.1755x over previous
#include <cuda_runtime.h>
#include <cuda_fp16.h>
#include <math.h>
#include <stdint.h>

#define HDIM 72
#define NSEQ 256
#define BATCH 16
#define ROWS 4096          // BATCH*NSEQ
#define SDIM 13
#define HP 88              // half pitch: row-start bank (44r)%32 distinct -> ldmatrix conflict-free

// ---------------- device scratch (static, no runtime alloc) ----------------
__device__ float  d_A [ROWS*HDIM];
__device__ float  d_Bm[ROWS*HDIM];      // UNSCALED (scale folded into k_main build)
__device__ float  d_Rn[ROWS];
__device__ float  d_Rd[ROWS];
__device__ float  d_S5[5];              // Sn, Sd, Snn, Sdd, Snd
__device__ float  d_SA[BATCH*HDIM];     // atomic accum (zeroed in k_zero)
__device__ float  d_SB[BATCH*HDIM];
__device__ float  d_T6[6*HDIM];
__device__ float  d_bn1[2*HDIM];        // scale, shift
__device__ float  d_r1s[HDIM];          // sc*r1
__device__ float  d_r2s[HDIM];          // sc*r2
__device__ float  d_magg[ROWS*HDIM];
__device__ float  d_y0 [ROWS*HDIM];
__device__ float  d_bn2[2*HDIM];
__device__ float  d_bn2acc[2*HDIM];     // sum, sumsq of y0 per channel
__device__ __align__(16) __half d_W2h[HDIM*HP];   // We2^T fp16 [n][k], k padded
__device__ __align__(16) __half d_W1h[HDIM*HP];   // Wx1^T fp16 [n][k]

__device__ __forceinline__ float psif(float x){
    return copysignf(log1pf(fabsf(x)), x);
}
__device__ __forceinline__ float wsum(float v){
    v += __shfl_xor_sync(0xffffffffu, v, 16);
    v += __shfl_xor_sync(0xffffffffu, v, 8);
    v += __shfl_xor_sync(0xffffffffu, v, 4);
    v += __shfl_xor_sync(0xffffffffu, v, 2);
    v += __shfl_xor_sync(0xffffffffu, v, 1);
    return v;
}
__device__ __forceinline__ uint32_t smem_u32(const void* p){
    uint32_t a;
    asm("{ .reg .u64 t; cvta.to.shared.u64 t, %1; cvt.u32.u64 %0, t; }" : "=r"(a) : "l"(p));
    return a;
}
__device__ __forceinline__ void mma16(float* c, uint32_t a0, uint32_t a1, uint32_t a2,
                                      uint32_t a3, uint32_t b0, uint32_t b1){
    asm volatile("mma.sync.aligned.m16n8k16.row.col.f32.f16.f16.f32 "
        "{%0,%1,%2,%3}, {%4,%5,%6,%7}, {%8,%9}, {%0,%1,%2,%3};"
        : "+f"(c[0]), "+f"(c[1]), "+f"(c[2]), "+f"(c[3])
        : "r"(a0), "r"(a1), "r"(a2), "r"(a3), "r"(b0), "r"(b1));
}
__device__ __forceinline__ void ldsm_x4(uint32_t& r0, uint32_t& r1, uint32_t& r2,
                                        uint32_t& r3, uint32_t addr){
    asm volatile("ldmatrix.sync.aligned.m8n8.x4.shared.b16 {%0,%1,%2,%3}, [%4];"
        : "=r"(r0), "=r"(r1), "=r"(r2), "=r"(r3) : "r"(addr));
}
__device__ __forceinline__ void ldsm_x2(uint32_t& r0, uint32_t& r1, uint32_t addr){
    asm volatile("ldmatrix.sync.aligned.m8n8.x2.shared.b16 {%0,%1}, [%2];"
        : "=r"(r0), "=r"(r1) : "r"(addr));
}

// ---------------- zero accumulators + fp16 weight transpose ----------------
__global__ void k_zero(const float* __restrict__ We2, const float* __restrict__ Wx1){
    int t = blockIdx.x*256 + threadIdx.x;    // grid 8 x 256 = 2048
    if (t < 5) d_S5[t] = 0.f;
    for (int i = t; i < 6*HDIM; i += 2048) d_T6[i] = 0.f;
    for (int i = t; i < 2*HDIM; i += 2048) d_bn2acc[i] = 0.f;
    for (int i = t; i < BATCH*HDIM; i += 2048){ d_SA[i] = 0.f; d_SB[i] = 0.f; }
    for (int i = t; i < HDIM*80; i += 2048){
        int k = i / HDIM, n = i - (i/HDIM)*HDIM;
        __half w2 = (k < HDIM) ? __float2half_rn(We2[k*HDIM + n]) : __half(0.f);
        __half w1 = (k < HDIM) ? __float2half_rn(Wx1[k*HDIM + n]) : __half(0.f);
        d_W2h[n*HP + k] = w2;
        d_W1h[n*HP + k] = w1;
    }
}

// ---------------- geometry moments ----------------
__global__ void k_geom(const float* __restrict__ p){
    int i = blockIdx.x, b = blockIdx.y;
    int row = b*NSEQ + i;
    int j = threadIdx.x;
    __shared__ float4 pi4s;
    __shared__ float red[8][5];
    if (j == 0) pi4s = reinterpret_cast<const float4*>(p)[row];
    __syncthreads();
    float4 pi = pi4s;
    float4 pj = reinterpret_cast<const float4*>(p)[b*NSEQ + j];
    float d0=pi.x-pj.x, d1=pi.y-pj.y, d2=pi.z-pj.z, d3=pi.w-pj.w;
    float n  = psif(d1*d1 + d2*d2 + d3*d3 - d0*d0);
    float dt = psif(pi.x*pj.x - pi.y*pj.y - pi.z*pj.z - pi.w*pj.w);
    float v0=wsum(n), v1=wsum(dt), v2=wsum(n*n), v3=wsum(dt*dt), v4=wsum(n*dt);
    int lane = j & 31, w = j >> 5;
    if (lane==0){ red[w][0]=v0; red[w][1]=v1; red[w][2]=v2; red[w][3]=v3; red[w][4]=v4; }
    __syncthreads();
    if (j == 0){
        float s0=0,s1=0,s2=0,s3=0,s4=0;
        for (int q=0;q<8;q++){ s0+=red[q][0]; s1+=red[q][1]; s2+=red[q][2]; s3+=red[q][3]; s4+=red[q][4]; }
        d_Rn[row]=s0; d_Rd[row]=s1;
        atomicAdd(&d_S5[0], s0); atomicAdd(&d_S5[1], s1);
        atomicAdd(&d_S5[2], s2); atomicAdd(&d_S5[3], s3); atomicAdd(&d_S5[4], s4);
    }
}

// ---------------- A/B (8 rows/block) + fused per-channel moments ----------------
__global__ void k_AB(const float* __restrict__ h, const float* __restrict__ We1){
    __shared__ float Ws[144*HDIM];
    __shared__ float hs[8*HDIM];
    __shared__ float rnS[8], rdS[8];
    int t = threadIdx.x;   // 256
    int row0 = blockIdx.x*8;
    int b = blockIdx.x >> 5;            // 32 blocks per batch
    for (int idx=t; idx<144*HDIM; idx+=256) Ws[idx] = We1[idx];
    for (int idx=t; idx<8*HDIM; idx+=256)   hs[idx] = h[row0*HDIM + idx];
    if (t < 8){ rnS[t] = d_Rn[row0 + t]; rdS[t] = d_Rd[row0 + t]; }
    __syncthreads();
    if (t < 144){
        bool isA = t < HDIM;
        int c = isA ? t : t - HDIM;
        const float* Wcol = Ws + (isA ? 0 : HDIM*HDIM) + c;
        float sum=0.f, sq=0.f, srn=0.f, srd=0.f;
        #pragma unroll 2
        for (int r=0;r<8;r++){
            const float* hr = hs + r*HDIM;
            float acc = 0.f;
            #pragma unroll 8
            for (int k=0;k<HDIM;k++) acc = fmaf(hr[k], Wcol[k*HDIM], acc);
            if (isA) d_A [(row0+r)*HDIM + c] = acc;
            else     d_Bm[(row0+r)*HDIM + c] = acc;
            sum += acc;
            sq  = fmaf(acc, acc, sq);
            srn = fmaf(acc, rnS[r], srn);
            srd = fmaf(acc, rdS[r], srd);
        }
        if (isA){
            atomicAdd(&d_SA[b*HDIM + c], sum);
            atomicAdd(&d_T6[0*HDIM + c], sq);
            atomicAdd(&d_T6[2*HDIM + c], srn);
            atomicAdd(&d_T6[3*HDIM + c], srd);
        } else {
            atomicAdd(&d_SB[b*HDIM + c], sum);
            atomicAdd(&d_T6[1*HDIM + c], sq);
            atomicAdd(&d_T6[4*HDIM + c], srn);
            atomicAdd(&d_T6[5*HDIM + c], srd);
        }
    }
}

// ---------------- BN1 finalize (exact algebra) + fold sc into r1,r2 ----------------
__global__ void k_bn1(const float* __restrict__ We1, const float* __restrict__ g1,
                      const float* __restrict__ b1){
    int c = threadIdx.x;
    if (c >= HDIM) return;
    float r1 = We1[144*HDIM + c], r2 = We1[145*HDIM + c];
    float SAt=0.f, SBt=0.f, cross=0.f;
    for (int b=0;b<BATCH;b++){
        float sa = d_SA[b*HDIM+c], sb = d_SB[b*HDIM+c];
        SAt += sa; SBt += sb; cross += sa*sb;
    }
    float Sn=d_S5[0], Sd=d_S5[1], Snn=d_S5[2], Sdd=d_S5[3], Snd=d_S5[4];
    float sumx  = 256.f*(SAt + SBt) + r1*Sn + r2*Sd;
    float sumx2 = 256.f*(d_T6[c] + d_T6[HDIM+c])
                + r1*r1*Snn + r2*r2*Sdd
                + 2.f*cross
                + 2.f*r1*(d_T6[2*HDIM+c] + d_T6[4*HDIM+c])
                + 2.f*r2*(d_T6[3*HDIM+c] + d_T6[5*HDIM+c])
                + 2.f*r1*r2*Snd;
    const float P = 1048576.f;
    float mu  = sumx / P;
    float var = sumx2 / P - mu*mu;
    float sc  = g1[c] * rsqrtf(var + 1e-5f);
    d_bn1[c]        = sc;
    d_bn1[HDIM + c] = b1[c] - mu*sc;
    d_r1s[c] = r1*sc;
    d_r2s[c] = r2*sc;
}

// ---------------- main pairwise kernel ----------------
// SMEM: Ts[256][HP] half | W2c[72][HP] half | W1c[72][HP] half | vectors
#define TS_OFF  0
#define TS_BYTES (256*HP*2)
#define W2_OFF  (TS_OFF + TS_BYTES)
#define W1_OFF  (W2_OFF + HDIM*HP*2)
#define VEC_OFF (W1_OFF + HDIM*HP*2)

struct KVecs {
    float Ash[HDIM], Scv[HDIM], r1s[HDIM], r2s[HDIM];
    float be2v[HDIM], bx1v[HDIM], Wmv[HDIM], Wx2v[HDIM];
    float mg[HDIM];
    float aggred[8][4];
    float pis[4];
    float bmv;
};
#define KSMEM_TOTAL (VEC_OFF + (int)sizeof(KVecs))

__global__ __launch_bounds__(256, 2) void k_main(
    const float* __restrict__ p,
    const float* __restrict__ be2, const float* __restrict__ Wm,
    const float* __restrict__ bm,  const float* __restrict__ bx1,
    const float* __restrict__ Wx2, float* __restrict__ out_p)
{
    extern __shared__ unsigned char sm[];
    __half* Ts  = reinterpret_cast<__half*>(sm + TS_OFF);
    __half* W2c = reinterpret_cast<__half*>(sm + W2_OFF);
    __half* W1c = reinterpret_cast<__half*>(sm + W1_OFF);
    KVecs*  V   = reinterpret_cast<KVecs*>(sm + VEC_OFF);
    const int i = blockIdx.x, b = blockIdx.y;
    const int row = b*NSEQ + i;
    const int tid  = threadIdx.x;
    const int wid  = tid >> 5;       // 0..7
    const int lane = tid & 31;
    const int g    = lane >> 2;
    const int tig  = lane & 3;
    const int r0   = wid*32;         // warp's 32 rows

    // ---- init: copy pre-transposed fp16 weights, vectors, pad ----
    {
        uint4* dst2 = reinterpret_cast<uint4*>(W2c);
        uint4* dst1 = reinterpret_cast<uint4*>(W1c);
        const uint4* s2 = reinterpret_cast<const uint4*>(d_W2h);
        const uint4* s1 = reinterpret_cast<const uint4*>(d_W1h);
        for (int t = tid; t < HDIM*HP/8; t += 256){ dst2[t] = s2[t]; dst1[t] = s1[t]; }
    }
    *reinterpret_cast<uint4*>(Ts + tid*HP + 72) = make_uint4(0u,0u,0u,0u);  // K pad
    if (tid < HDIM){
        float sc = d_bn1[tid];
        V->Ash[tid]  = fmaf(d_A[row*HDIM + tid], sc, d_bn1[HDIM + tid]);
        V->Scv[tid]  = sc;
        V->r1s[tid]  = d_r1s[tid];
        V->r2s[tid]  = d_r2s[tid];
        V->be2v[tid] = be2[tid];
        V->bx1v[tid] = bx1[tid];
        V->Wmv[tid]  = Wm[tid];
        V->Wx2v[tid] = Wx2[tid];
        V->mg[tid]   = 0.f;
    }
    if (tid < 4)  V->pis[tid] = p[row*4 + tid];
    if (tid == 0) V->bmv = bm[0];
    __syncthreads();

    const float bmv = V->bmv;
    const float4 pis4 = *reinterpret_cast<const float4*>(V->pis);

    // ---- build all 256 rows: thread t builds row t (scale of Bm folded in) ----
    {
        float4 pj = reinterpret_cast<const float4*>(p)[b*NSEQ + tid];
        float e0=pis4.x-pj.x, e1=pis4.y-pj.y, e2=pis4.z-pj.z, e3=pis4.w-pj.w;
        float nn = psif(e1*e1 + e2*e2 + e3*e3 - e0*e0);
        float dd = psif(pis4.x*pj.x - pis4.y*pj.y - pis4.z*pj.z - pis4.w*pj.w);
        const float4* B4 = reinterpret_cast<const float4*>(d_Bm + (b*NSEQ + tid)*HDIM);
        const float4* A4 = reinterpret_cast<const float4*>(V->Ash);
        const float4* S4 = reinterpret_cast<const float4*>(V->Scv);
        const float4* U4 = reinterpret_cast<const float4*>(V->r1s);
        const float4* W4 = reinterpret_cast<const float4*>(V->r2s);
        #pragma unroll
        for (int q = 0; q < 18; ++q){
            float4 bv = B4[q];
            float4 av = A4[q], sv = S4[q], uv = U4[q], wv = W4[q];
            float v0 = fmaxf(fmaf(sv.x, bv.x, av.x) + nn*uv.x + dd*wv.x, 0.f);
            float v1 = fmaxf(fmaf(sv.y, bv.y, av.y) + nn*uv.y + dd*wv.y, 0.f);
            float v2 = fmaxf(fmaf(sv.z, bv.z, av.z) + nn*uv.z + dd*wv.z, 0.f);
            float v3 = fmaxf(fmaf(sv.w, bv.w, av.w) + nn*uv.w + dd*wv.w, 0.f);
            __half2 hlo = __floats2half2_rn(v0, v1);
            __half2 hhi = __floats2half2_rn(v2, v3);
            uint2 u; u.x = *reinterpret_cast<uint32_t*>(&hlo); u.y = *reinterpret_cast<uint32_t*>(&hhi);
            *reinterpret_cast<uint2*>(Ts + tid*HP + q*4) = u;
        }
    }
    __syncwarp();

    // ldmatrix addresses
    const int lr  = lane & 15;
    const int kh  = (lane & 16) ? 8 : 0;
    const uint32_t aAddr0 = smem_u32(Ts) + (uint32_t)(((r0 + lr)*HP + kh)*2);
    const uint32_t aAddr1 = aAddr0 + 16*HP*2;
    const int bl  = lane & 7;
    const int bko = (lane & 8) ? 8 : 0;
    const uint32_t b2Addr = smem_u32(W2c) + (uint32_t)((bl*HP + bko)*2);
    const uint32_t b1Addr = smem_u32(W1c) + (uint32_t)((bl*HP + bko)*2);

    float colsum[9][2];
    #pragma unroll
    for (int nt=0;nt<9;nt++){ colsum[nt][0]=0.f; colsum[nt][1]=0.f; }
    float agg0=0.f, agg1=0.f, agg2=0.f, agg3=0.f;
    float acc[2][9][4];

    // ================= GEMM1: acc = T @ We2 =================
    #pragma unroll
    for (int ch=0;ch<2;ch++)
        #pragma unroll
        for (int nt=0;nt<9;nt++){ acc[ch][nt][0]=0.f; acc[ch][nt][1]=0.f; acc[ch][nt][2]=0.f; acc[ch][nt][3]=0.f; }
    #pragma unroll
    for (int kk=0;kk<5;kk++){
        uint32_t a[2][4];
        ldsm_x4(a[0][0], a[0][1], a[0][2], a[0][3], aAddr0 + kk*32);
        ldsm_x4(a[1][0], a[1][1], a[1][2], a[1][3], aAddr1 + kk*32);
        #pragma unroll
        for (int nt=0;nt<9;nt++){
            uint32_t b0, b1;
            ldsm_x2(b0, b1, b2Addr + nt*(8*HP*2) + kk*32);
            mma16(acc[0][nt], a[0][0], a[0][1], a[0][2], a[0][3], b0, b1);
            mma16(acc[1][nt], a[1][0], a[1][1], a[1][2], a[1][3], b0, b1);
        }
    }
    __syncwarp();

    // ---- epi1: m = relu(acc+be2); w = sigmoid(m.Wm+bm); wm = m*w -> Ts ----
    #pragma unroll
    for (int ch=0;ch<2;ch++){
        float dot0 = 0.f, dot1 = 0.f;
        #pragma unroll
        for (int nt=0;nt<9;nt++){
            int cb = nt*8 + 2*tig;
            float2 bb = *reinterpret_cast<const float2*>(V->be2v + cb);
            float2 wm2 = *reinterpret_cast<const float2*>(V->Wmv + cb);
            float m0 = fmaxf(acc[ch][nt][0] + bb.x, 0.f);
            float m1 = fmaxf(acc[ch][nt][1] + bb.y, 0.f);
            float m2 = fmaxf(acc[ch][nt][2] + bb.x, 0.f);
            float m3 = fmaxf(acc[ch][nt][3] + bb.y, 0.f);
            acc[ch][nt][0]=m0; acc[ch][nt][1]=m1; acc[ch][nt][2]=m2; acc[ch][nt][3]=m3;
            dot0 = fmaf(m0, wm2.x, fmaf(m1, wm2.y, dot0));
            dot1 = fmaf(m2, wm2.x, fmaf(m3, wm2.y, dot1));
        }
        dot0 += __shfl_xor_sync(0xffffffffu, dot0, 1);
        dot0 += __shfl_xor_sync(0xffffffffu, dot0, 2);
        dot1 += __shfl_xor_sync(0xffffffffu, dot1, 1);
        dot1 += __shfl_xor_sync(0xffffffffu, dot1, 2);
        float w0 = 1.f / (1.f + expf(-(dot0 + bmv)));
        float w1 = 1.f / (1.f + expf(-(dot1 + bmv)));
        const int rl = r0 + ch*16 + g;
        #pragma unroll
        for (int nt=0;nt<9;nt++){
            float l0 = acc[ch][nt][0]*w0;
            float l1 = acc[ch][nt][1]*w0;
            float h0 = acc[ch][nt][2]*w1;
            float h1 = acc[ch][nt][3]*w1;
            colsum[nt][0] += l0 + h0;
            colsum[nt][1] += l1 + h1;
            int cb = nt*8 + 2*tig;
            __half2 lo = __floats2half2_rn(l0, l1);
            __half2 hi = __floats2half2_rn(h0, h1);
            *reinterpret_cast<uint32_t*>(Ts + rl*HP + cb)     = *reinterpret_cast<uint32_t*>(&lo);
            *reinterpret_cast<uint32_t*>(Ts + (rl+8)*HP + cb) = *reinterpret_cast<uint32_t*>(&hi);
        }
    }
    __syncwarp();

    // ================= GEMM2: acc = wm @ Wx1 =================
    #pragma unroll
    for (int ch=0;ch<2;ch++)
        #pragma unroll
        for (int nt=0;nt<9;nt++){ acc[ch][nt][0]=0.f; acc[ch][nt][1]=0.f; acc[ch][nt][2]=0.f; acc[ch][nt][3]=0.f; }
    #pragma unroll
    for (int kk=0;kk<5;kk++){
        uint32_t a[2][4];
        ldsm_x4(a[0][0], a[0][1], a[0][2], a[0][3], aAddr0 + kk*32);
        ldsm_x4(a[1][0], a[1][1], a[1][2], a[1][3], aAddr1 + kk*32);
        #pragma unroll
        for (int nt=0;nt<9;nt++){
            uint32_t b0, b1;
            ldsm_x2(b0, b1, b1Addr + nt*(8*HP*2) + kk*32);
            mma16(acc[0][nt], a[0][0], a[0][1], a[0][2], a[0][3], b0, b1);
            mma16(acc[1][nt], a[1][0], a[1][1], a[1][2], a[1][3], b0, b1);
        }
    }

    // ---- epi2: u = relu(acc+bx1); xw = u.Wx2; tig0 lanes do their rows' aggs ----
    #pragma unroll
    for (int ch=0;ch<2;ch++){
        float px0 = 0.f, px1 = 0.f;
        #pragma unroll
        for (int nt=0;nt<9;nt++){
            int cb = nt*8 + 2*tig;
            float2 bb = *reinterpret_cast<const float2*>(V->bx1v + cb);
            float2 wx = *reinterpret_cast<const float2*>(V->Wx2v + cb);
            float u0 = fmaxf(acc[ch][nt][0] + bb.x, 0.f);
            float u1 = fmaxf(acc[ch][nt][1] + bb.y, 0.f);
            float u2 = fmaxf(acc[ch][nt][2] + bb.x, 0.f);
            float u3 = fmaxf(acc[ch][nt][3] + bb.y, 0.f);
            px0 = fmaf(u0, wx.x, fmaf(u1, wx.y, px0));
            px1 = fmaf(u2, wx.x, fmaf(u3, wx.y, px1));
        }
        px0 += __shfl_xor_sync(0xffffffffu, px0, 1);
        px0 += __shfl_xor_sync(0xffffffffu, px0, 2);
        px1 += __shfl_xor_sync(0xffffffffu, px1, 1);
        px1 += __shfl_xor_sync(0xffffffffu, px1, 2);
        if (tig == 0){
            int jl = r0 + ch*16 + g;
            float4 pj = reinterpret_cast<const float4*>(p)[b*NSEQ + jl];
            agg0 += fminf(fmaxf((pis4.x - pj.x)*px0, -100.f), 100.f);
            agg1 += fminf(fmaxf((pis4.y - pj.y)*px0, -100.f), 100.f);
            agg2 += fminf(fmaxf((pis4.z - pj.z)*px0, -100.f), 100.f);
            agg3 += fminf(fmaxf((pis4.w - pj.w)*px0, -100.f), 100.f);
            float4 ph = reinterpret_cast<const float4*>(p)[b*NSEQ + jl + 8];
            agg0 += fminf(fmaxf((pis4.x - ph.x)*px1, -100.f), 100.f);
            agg1 += fminf(fmaxf((pis4.y - ph.y)*px1, -100.f), 100.f);
            agg2 += fminf(fmaxf((pis4.z - ph.z)*px1, -100.f), 100.f);
            agg3 += fminf(fmaxf((pis4.w - ph.w)*px1, -100.f), 100.f);
        }
    }

    // ---- magg: reduce colsum over g-lanes, atomic into V->mg ----
    #pragma unroll
    for (int nt=0;nt<9;nt++)
        #pragma unroll
        for (int d=0;d<2;d++){
            float v = colsum[nt][d];
            v += __shfl_xor_sync(0xffffffffu, v, 4);
            v += __shfl_xor_sync(0xffffffffu, v, 8);
            v += __shfl_xor_sync(0xffffffffu, v, 16);
            if (g == 0) atomicAdd(&V->mg[nt*8 + 2*tig + d], v);
        }
    // ---- agg reduce across warps ----
    {
        float s0=wsum(agg0), s1=wsum(agg1), s2=wsum(agg2), s3=wsum(agg3);
        if (lane==0){ V->aggred[wid][0]=s0; V->aggred[wid][1]=s1; V->aggred[wid][2]=s2; V->aggred[wid][3]=s3; }
    }
    __syncthreads();
    if (tid < HDIM) d_magg[row*HDIM + tid] = V->mg[tid];
    if (tid < 4){
        float s = 0.f;
        #pragma unroll
        for (int w=0;w<8;w++) s += V->aggred[w][tid];
        out_p[row*4 + tid] = V->pis[tid] + (s * (1.f/256.f)) * 0.001f;
    }
}

// ---------------- h-path: y0 = [h,magg,s] @ Wh1 + bh1 (64 rows/block, tiled) ----
__global__ __launch_bounds__(256) void k_y0(
    const float* __restrict__ h, const float* __restrict__ s,
    const float* __restrict__ Wh1, const float* __restrict__ bh1)
{
    extern __shared__ float ysm[];
    float* Ws   = ysm;                 // 157*72
    float* hinS = ysm + 157*HDIM;      // 64 rows, pitch 161
    int t = threadIdx.x;
    int row0 = blockIdx.x * 64;
    for (int idx = t; idx < 157*HDIM; idx += 256) Ws[idx] = Wh1[idx];
    for (int idx = t; idx < 64*HDIM; idx += 256){
        int r = idx / HDIM, c = idx - r*HDIM;
        hinS[r*161 + c]        = h[(row0+r)*HDIM + c];
        hinS[r*161 + HDIM + c] = d_magg[(row0+r)*HDIM + c];
    }
    for (int idx = t; idx < 64*SDIM; idx += 256){
        int r = idx / SDIM, c = idx - r*SDIM;
        hinS[r*161 + 2*HDIM + c] = s[(row0+r)*SDIM + c];
    }
    __syncthreads();
    int tr = t & 31, cg = t >> 5;
    int c0 = cg*9;
    float acc0[9], acc1[9];
    #pragma unroll
    for (int m=0;m<9;m++){ float bv = bh1[c0+m]; acc0[m] = bv; acc1[m] = bv; }
    const float* h0p = hinS + tr*161;
    const float* h1p = hinS + (tr+32)*161;
    #pragma unroll 4
    for (int k=0;k<157;k++){
        float x0 = h0p[k], x1 = h1p[k];
        const float* wr = Ws + k*HDIM + c0;
        #pragma unroll
        for (int m=0;m<9;m++){ float w = wr[m]; acc0[m] = fmaf(x0,w,acc0[m]); acc1[m] = fmaf(x1,w,acc1[m]); }
    }
    #pragma unroll
    for (int m=0;m<9;m++){
        d_y0[(row0+tr)*HDIM + c0+m]    = acc0[m];
        d_y0[(row0+tr+32)*HDIM + c0+m] = acc1[m];
        float sv = acc0[m] + acc1[m];
        float qv = acc0[m]*acc0[m] + acc1[m]*acc1[m];
        sv = wsum(sv);
        qv = wsum(qv);
        if (tr == 0){
            atomicAdd(&d_bn2acc[c0+m], sv);
            atomicAdd(&d_bn2acc[HDIM + c0+m], qv);
        }
    }
}

// ---------------- BN2 finalize ----------------
__global__ void k_bn2f(const float* __restrict__ gh, const float* __restrict__ bh){
    int c = threadIdx.x;
    if (c >= HDIM) return;
    float mu  = d_bn2acc[c] / 4096.f;
    float var = d_bn2acc[HDIM + c] / 4096.f - mu*mu;
    float sc  = gh[c] * rsqrtf(var + 1e-5f);
    d_bn2[c]        = sc;
    d_bn2[HDIM + c] = bh[c] - mu*sc;
}

// ---------------- h_out = h + relu(bn2(y0)) @ Wh2 + bh2 (64 rows/block) ----------
__global__ __launch_bounds__(256) void k_hout(
    const float* __restrict__ h, const float* __restrict__ Wh2,
    const float* __restrict__ bh2, float* __restrict__ out_h)
{
    __shared__ float Ws[HDIM*HDIM];
    __shared__ float yrS[64*73];
    int t = threadIdx.x;
    int row0 = blockIdx.x * 64;
    for (int idx=t; idx<HDIM*HDIM; idx+=256) Ws[idx] = Wh2[idx];
    for (int idx=t; idx<64*HDIM; idx+=256){
        int r = idx / HDIM, c = idx - r*HDIM;
        yrS[r*73 + c] = fmaxf(fmaf(d_y0[(row0+r)*HDIM + c], d_bn2[c], d_bn2[HDIM + c]), 0.f);
    }
    __syncthreads();
    int tr = t & 31, cg = t >> 5;
    int c0 = cg*9;
    float acc0[9], acc1[9];
    #pragma unroll
    for (int m=0;m<9;m++){ float bv = bh2[c0+m]; acc0[m] = bv; acc1[m] = bv; }
    const float* y0p = yrS + tr*73;
    const float* y1p = yrS + (tr+32)*73;
    #pragma unroll 4
    for (int k=0;k<HDIM;k++){
        float x0 = y0p[k], x1 = y1p[k];
        const float* wr = Ws + k*HDIM + c0;
        #pragma unroll
        for (int m=0;m<9;m++){ float w = wr[m]; acc0[m] = fmaf(x0,w,acc0[m]); acc1[m] = fmaf(x1,w,acc1[m]); }
    }
    #pragma unroll
    for (int m=0;m<9;m++){
        out_h[(row0+tr)*HDIM + c0+m]    = h[(row0+tr)*HDIM + c0+m]    + acc0[m];
        out_h[(row0+tr+32)*HDIM + c0+m] = h[(row0+tr+32)*HDIM + c0+m] + acc1[m];
    }
}

// ---------------- launch ----------------
extern "C" void kernel_launch(void* const* d_in, const int* in_sizes, int n_in,
                              void* d_out, int out_size){
    const float* h   = (const float*)d_in[0];
    const float* p   = (const float*)d_in[1];
    const float* s   = (const float*)d_in[2];
    const float* We1 = (const float*)d_in[3];
    const float* g1  = (const float*)d_in[4];
    const float* b1  = (const float*)d_in[5];
    const float* We2 = (const float*)d_in[6];
    const float* be2 = (const float*)d_in[7];
    const float* Wm  = (const float*)d_in[8];
    const float* bm  = (const float*)d_in[9];
    const float* Wx1 = (const float*)d_in[10];
    const float* bx1 = (const float*)d_in[11];
    const float* Wx2 = (const float*)d_in[12];
    const float* Wh1 = (const float*)d_in[13];
    const float* bh1 = (const float*)d_in[14];
    const float* gh  = (const float*)d_in[15];
    const float* bh  = (const float*)d_in[16];
    const float* Wh2 = (const float*)d_in[17];
    const float* bh2 = (const float*)d_in[18];
    float* out   = (float*)d_out;
    float* out_h = out;                 // (B,N,H) first
    float* out_p = out + ROWS*HDIM;     // then (B,N,4)

    const int y0smem = (157*HDIM + 64*161) * 4;
    cudaFuncSetAttribute(k_main, cudaFuncAttributeMaxDynamicSharedMemorySize, KSMEM_TOTAL);
    cudaFuncSetAttribute(k_y0,   cudaFuncAttributeMaxDynamicSharedMemorySize, y0smem);

    k_zero <<<8, 256>>>(We2, Wx1);
    k_geom <<<dim3(NSEQ, BATCH), NSEQ>>>(p);
    k_AB   <<<ROWS/8, 256>>>(h, We1);
    k_bn1  <<<1, 128>>>(We1, g1, b1);
    k_main <<<dim3(NSEQ, BATCH), 256, KSMEM_TOTAL>>>(p, be2, Wm, bm, bx1, Wx2, out_p);
    k_y0   <<<ROWS/64, 256, y0smem>>>(h, s, Wh1, bh1);
    k_bn2f <<<1, 128>>>(gh, bh);
    k_hout <<<ROWS/64, 256>>>(h, Wh2, bh2, out_h);
}